// round 2
// baseline (speedup 1.0000x reference)
#include <cuda_runtime.h>

#define BB 128
#define TT 4096
#define NN 32
#define FULL 0xffffffffu
#define UF 8          // prefetch depth / unroll for fb recursions
#define NCHUNK 8      // t-chunks per batch in combine
#define CHUNK (TT / NCHUNK)

// Scratch tapes for scaled forward/backward messages (scale cancels in ratios).
__device__ float g_a[(size_t)BB * TT * NN];
__device__ float g_b[(size_t)BB * TT * NN];
__device__ float g_partial[BB][NCHUNK];

// ---------------------------------------------------------------------------
// Kernel 1: forward and backward recursions. One block per batch, 2 warps:
// warp 0 = forward chain, warp 1 = backward chain. Lane = state.
// Probability-domain recursion with per-step rescale by lane-0 value; the
// per-t scale cancels in the final marginal ratio, so no log/lse anywhere.
// Deep prefetch (UF ahead) keeps MLP=8 on the pot stream so DRAM latency is
// hidden behind the ~85-cycle serial shuffle/FMA step.
// ---------------------------------------------------------------------------
__global__ void __launch_bounds__(64, 16)
fb_kernel(const float* __restrict__ pots,
          const int*   __restrict__ lengths,
          const float* __restrict__ trans)
{
    const int lane   = threadIdx.x & 31;
    const int warp   = threadIdx.x >> 5;
    const int b      = blockIdx.x;
    const int len    = lengths[b];
    const float* pot = pots + (size_t)b * TT * NN;

    float E[NN];

    if (warp == 0) {
        // ----------------- forward: lane j holds exp(trans[:, j]) ----------
        #pragma unroll
        for (int i = 0; i < NN; i++) E[i] = __expf(trans[i * NN + lane]);

        float* A = g_a + (size_t)b * TT * NN;

        float a = __expf(pot[lane]);          // t = 0
        A[lane] = a;

        float pf[UF];
        #pragma unroll
        for (int u = 0; u < UF; u++) {
            int t = 1 + u; if (t > TT - 1) t = TT - 1;
            pf[u] = pot[(size_t)t * NN + lane];
        }

        for (int t0 = 1; t0 < len; t0 += UF) {
            #pragma unroll
            for (int u = 0; u < UF; u++) {
                const int t = t0 + u;
                float P = __expf(pf[u]);
                int tp = t + UF; if (tp > TT - 1) tp = TT - 1;
                pf[u] = pot[(size_t)tp * NN + lane];   // prefetch UF ahead

                float acc0 = 0.f, acc1 = 0.f, acc2 = 0.f, acc3 = 0.f;
                float r = 0.f;
                #pragma unroll
                for (int i = 0; i < NN; i += 4) {
                    float v0 = __shfl_sync(FULL, a, i + 0);
                    float v1 = __shfl_sync(FULL, a, i + 1);
                    float v2 = __shfl_sync(FULL, a, i + 2);
                    float v3 = __shfl_sync(FULL, a, i + 3);
                    if (i == 0) r = __frcp_rn(v0);     // renorm, off critical path
                    acc0 = fmaf(v0, E[i + 0], acc0);
                    acc1 = fmaf(v1, E[i + 1], acc1);
                    acc2 = fmaf(v2, E[i + 2], acc2);
                    acc3 = fmaf(v3, E[i + 3], acc3);
                }
                float s = (acc0 + acc1) + (acc2 + acc3);
                float anew = s * r * P;
                // steps t >= len are tail garbage: never stored, values stay
                // finite/positive so no NaN can propagate (and a is unused after).
                a = anew;
                if (t < len) A[(size_t)t * NN + lane] = anew;
            }
        }
        if (lane == 0) ; // (no-op)
    } else {
        // ----------------- backward: lane i holds exp(trans[i, :]) ---------
        #pragma unroll
        for (int j = 0; j < NN; j++) E[j] = __expf(trans[lane * NN + j]);

        float* Bv = g_b + (size_t)b * TT * NN;

        float bv = 1.0f;                      // beta_{len-1} = 1 (prob domain)
        Bv[(size_t)(len - 1) * NN + lane] = 1.0f;

        float pf[UF];
        #pragma unroll
        for (int u = 0; u < UF; u++) {
            int t = len - 1 - u; if (t < 0) t = 0;
            pf[u] = pot[(size_t)t * NN + lane];
        }

        for (int t0 = len - 1; t0 >= 1; t0 -= UF) {
            #pragma unroll
            for (int u = 0; u < UF; u++) {
                const int t = t0 - u;
                float P = __expf(pf[u]);
                int tp = t - UF; if (tp < 0) tp = 0;
                pf[u] = pot[(size_t)tp * NN + lane];   // prefetch UF ahead

                float uu = bv * P;

                float acc0 = 0.f, acc1 = 0.f, acc2 = 0.f, acc3 = 0.f;
                float r = 0.f;
                #pragma unroll
                for (int j = 0; j < NN; j += 4) {
                    float v0 = __shfl_sync(FULL, uu, j + 0);
                    float v1 = __shfl_sync(FULL, uu, j + 1);
                    float v2 = __shfl_sync(FULL, uu, j + 2);
                    float v3 = __shfl_sync(FULL, uu, j + 3);
                    if (j == 0) r = __frcp_rn(v0);
                    acc0 = fmaf(v0, E[j + 0], acc0);
                    acc1 = fmaf(v1, E[j + 1], acc1);
                    acc2 = fmaf(v2, E[j + 2], acc2);
                    acc3 = fmaf(v3, E[j + 3], acc3);
                }
                float s = (acc0 + acc1) + (acc2 + acc3);
                float bnew = s * r;
                bv = bnew;
                if (t >= 1) Bv[(size_t)(t - 1) * NN + lane] = bnew;
            }
        }
    }
}

// ---------------------------------------------------------------------------
// Kernel 2: combine partials. grid = (BB, NCHUNK); block (b, c) handles
// t in [c*CHUNK, (c+1)*CHUNK) intersect [0, len). Writes its own slot in
// g_partial (no atomics -> deterministic).
// p_t(y_t) = a_y * b_y / sum_k a_k b_k (per-t scales cancel).
// ---------------------------------------------------------------------------
__global__ void __launch_bounds__(256)
combine_kernel(const int* __restrict__ y_true,
               const int* __restrict__ lengths)
{
    const int b   = blockIdx.x;
    const int c   = blockIdx.y;
    const int tid = threadIdx.x;
    const int len = lengths[b];

    const int t_lo = c * CHUNK;
    int t_hi = t_lo + CHUNK; if (t_hi > len) t_hi = len;

    const float* Ab = g_a + (size_t)b * TT * NN;
    const float* Bb = g_b + (size_t)b * TT * NN;
    const int*   Yb = y_true + (size_t)b * TT;

    float part = 0.f;
    for (int t = t_lo + tid; t < t_hi; t += 256) {
        const float4* A4 = reinterpret_cast<const float4*>(Ab + (size_t)t * NN);
        const float4* B4 = reinterpret_cast<const float4*>(Bb + (size_t)t * NN);
        int y = Yb[t];
        float s = 0.f;
        float py = 0.f;
        #pragma unroll
        for (int q = 0; q < 8; q++) {
            float4 av = __ldcs(&A4[q]);
            float4 bv = __ldcs(&B4[q]);
            s += av.x * bv.x + av.y * bv.y + av.z * bv.z + av.w * bv.w;
            int qy = y >> 2;
            if (q == qy) {
                float ae = (y & 3) == 0 ? av.x : (y & 3) == 1 ? av.y : (y & 3) == 2 ? av.z : av.w;
                float be = (y & 3) == 0 ? bv.x : (y & 3) == 1 ? bv.y : (y & 3) == 2 ? bv.z : bv.w;
                py = ae * be;
            }
        }
        part += __fdividef(py, s);
    }

    // block reduction
    #pragma unroll
    for (int off = 16; off > 0; off >>= 1)
        part += __shfl_down_sync(FULL, part, off);

    __shared__ float red[8];
    if ((tid & 31) == 0) red[tid >> 5] = part;
    __syncthreads();
    if (tid == 0) {
        float s = 0.f;
        #pragma unroll
        for (int w = 0; w < 8; w++) s += red[w];
        g_partial[b][c] = s;
    }
}

// ---------------------------------------------------------------------------
// Kernel 3: finalize dice per batch.
// ---------------------------------------------------------------------------
__global__ void finalize_kernel(const int* __restrict__ lengths,
                                float* __restrict__ out)
{
    const int b = threadIdx.x;
    if (b >= BB) return;
    float inter = 0.f;
    #pragma unroll
    for (int c = 0; c < NCHUNK; c++) inter += g_partial[b][c];
    float flen = (float)lengths[b];
    float dice = (2.0f * inter + 1.0f) / (2.0f * flen + 1.0f);
    out[b] = 1.0f - dice;
}

// ---------------------------------------------------------------------------
extern "C" void kernel_launch(void* const* d_in, const int* in_sizes, int n_in,
                              void* d_out, int out_size)
{
    const float* pots    = (const float*)d_in[0];   // [B,T,N] fp32
    const int*   y_true  = (const int*)  d_in[1];   // [B,T] int32
    const int*   lengths = (const int*)  d_in[2];   // [B] int32
    const float* trans   = (const float*)d_in[3];   // [N,N] fp32
    float* out = (float*)d_out;                     // [B] fp32

    fb_kernel<<<BB, 64>>>(pots, lengths, trans);
    combine_kernel<<<dim3(BB, NCHUNK), 256>>>(y_true, lengths);
    finalize_kernel<<<1, 128>>>(lengths, out);
}

// round 4
// speedup vs baseline: 2.2645x; 2.2645x over previous
#include <cuda_runtime.h>
#include <cstdint>

#define BB 128
#define TT 4096
#define NN 32
#define FULL 0xffffffffu
#define RING 8
#define NCHUNK 8
#define CHUNK (TT / NCHUNK)

// Scratch tapes for scaled forward/backward messages (scale cancels in ratios).
__device__ float g_a[(size_t)BB * TT * NN];
__device__ float g_b[(size_t)BB * TT * NN];
__device__ float g_partial[BB][NCHUNK];

__device__ __forceinline__ void cp_async4(unsigned int saddr, const float* gaddr) {
    asm volatile("cp.async.ca.shared.global [%0], [%1], 4;"
                 :: "r"(saddr), "l"(gaddr) : "memory");
}
__device__ __forceinline__ void cp_commit() {
    asm volatile("cp.async.commit_group;" ::: "memory");
}
__device__ __forceinline__ void cp_wait6() {
    asm volatile("cp.async.wait_group 6;" ::: "memory");
}

// ---------------------------------------------------------------------------
// Kernel 1: forward / backward recursions. One warp (= one block) per chain.
//   blocks [0, BB)    : forward  for batch = blockIdx.x
//   blocks [BB, 2*BB) : backward for batch = blockIdx.x - BB
// Lane = state. Probability-domain recursion, per-step rescale by lane-0
// (scale cancels in marginal ratios -> no log/lse anywhere).
// pot stream prefetched 7 steps ahead via cp.async into a smem ring: no
// destination registers, so ptxas cannot sink the loads -> true MLP=7.
// exp(pot) is software-pipelined one step early so MUFU/LDS latency is off
// the serial critical path.
// ---------------------------------------------------------------------------
__global__ void fb_kernel(const float* __restrict__ pots,
                          const int*   __restrict__ lengths,
                          const float* __restrict__ trans)
{
    __shared__ float ring[RING][NN];

    const int lane   = threadIdx.x;
    const int blk    = blockIdx.x;
    const bool fwd   = (blk < BB);
    const int b      = fwd ? blk : blk - BB;
    const int len    = lengths[b];
    const float* pot = pots + (size_t)b * TT * NN;

    const unsigned int rbase =
        (unsigned int)__cvta_generic_to_shared(&ring[0][0]) + lane * 4u;

    float E[NN];

    if (fwd) {
        // lane j holds exp(trans[:, j])
        #pragma unroll
        for (int i = 0; i < NN; i++) E[i] = __expf(trans[i * NN + lane]);

        float* A = g_a + (size_t)b * TT * NN;

        float a = __expf(pot[lane]);                 // t = 0
        A[lane] = a;

        // prologue: prefetch steps 1..7
        #pragma unroll
        for (int u = 0; u < 7; u++) {
            int t = 1 + u;
            int ti = (t < TT) ? t : (TT - 1);
            cp_async4(rbase + (unsigned int)((t & 7) * NN) * 4u,
                      pot + (size_t)ti * NN + lane);
            cp_commit();
        }
        cp_wait6();                                  // step 1 ready
        float Pcur = __expf(ring[1 & 7][lane]);

        for (int t = 1; t < len; ++t) {
            // prefetch step t+7
            int ti = t + 7; if (ti > TT - 1) ti = TT - 1;
            cp_async4(rbase + (unsigned int)(((t + 7) & 7) * NN) * 4u,
                      pot + (size_t)ti * NN + lane);
            cp_commit();

            float acc0 = 0.f, acc1 = 0.f, acc2 = 0.f, acc3 = 0.f;
            float r = 0.f;
            #pragma unroll
            for (int i = 0; i < NN; i += 4) {
                float v0 = __shfl_sync(FULL, a, i + 0);
                float v1 = __shfl_sync(FULL, a, i + 1);
                float v2 = __shfl_sync(FULL, a, i + 2);
                float v3 = __shfl_sync(FULL, a, i + 3);
                if (i == 0) r = __frcp_rn(v0);       // renorm, off critical path
                acc0 = fmaf(v0, E[i + 0], acc0);
                acc1 = fmaf(v1, E[i + 1], acc1);
                acc2 = fmaf(v2, E[i + 2], acc2);
                acc3 = fmaf(v3, E[i + 3], acc3);
            }
            float s = (acc0 + acc1) + (acc2 + acc3);
            a = s * r * Pcur;
            __stcs(&A[(size_t)t * NN + lane], a);

            // pipeline exp for step t+1 (latency hidden behind next step)
            cp_wait6();
            Pcur = __expf(ring[(t + 1) & 7][lane]);
        }
    } else {
        // lane i holds exp(trans[i, :])
        #pragma unroll
        for (int j = 0; j < NN; j++) E[j] = __expf(trans[lane * NN + j]);

        float* Bv = g_b + (size_t)b * TT * NN;

        float bv = 1.0f;                             // beta_{len-1}
        Bv[(size_t)(len - 1) * NN + lane] = 1.0f;

        // prologue: prefetch steps len-1 .. len-7
        #pragma unroll
        for (int u = 0; u < 7; u++) {
            int t = len - 1 - u;
            int ti = (t > 0) ? t : 0;
            cp_async4(rbase + (unsigned int)((t & 7) * NN) * 4u,
                      pot + (size_t)ti * NN + lane);
            cp_commit();
        }
        cp_wait6();                                  // step len-1 ready
        float Pcur = __expf(ring[(len - 1) & 7][lane]);

        for (int t = len - 1; t >= 1; --t) {
            int ti = t - 7; if (ti < 0) ti = 0;
            cp_async4(rbase + (unsigned int)(((t - 7) & 7) * NN) * 4u,
                      pot + (size_t)ti * NN + lane);
            cp_commit();

            float u = bv * Pcur;

            float acc0 = 0.f, acc1 = 0.f, acc2 = 0.f, acc3 = 0.f;
            float r = 0.f;
            #pragma unroll
            for (int j = 0; j < NN; j += 4) {
                float v0 = __shfl_sync(FULL, u, j + 0);
                float v1 = __shfl_sync(FULL, u, j + 1);
                float v2 = __shfl_sync(FULL, u, j + 2);
                float v3 = __shfl_sync(FULL, u, j + 3);
                if (j == 0) r = __frcp_rn(v0);
                acc0 = fmaf(v0, E[j + 0], acc0);
                acc1 = fmaf(v1, E[j + 1], acc1);
                acc2 = fmaf(v2, E[j + 2], acc2);
                acc3 = fmaf(v3, E[j + 3], acc3);
            }
            float s = (acc0 + acc1) + (acc2 + acc3);
            bv = s * r;
            __stcs(&Bv[(size_t)(t - 1) * NN + lane], bv);

            cp_wait6();
            Pcur = __expf(ring[(t - 1) & 7][lane]);
        }
    }
}

// ---------------------------------------------------------------------------
// Kernel 2: combine partials. grid (BB, NCHUNK); block (b,c) handles
// t in [c*CHUNK, (c+1)*CHUNK) ∩ [0,len). Deterministic per-slot partials.
// p_t(y_t) = a_y b_y / sum_k a_k b_k (per-t scales cancel).
// ---------------------------------------------------------------------------
__global__ void __launch_bounds__(256)
combine_kernel(const int* __restrict__ y_true,
               const int* __restrict__ lengths)
{
    const int b   = blockIdx.x;
    const int c   = blockIdx.y;
    const int tid = threadIdx.x;
    const int len = lengths[b];

    const int t_lo = c * CHUNK;
    int t_hi = t_lo + CHUNK; if (t_hi > len) t_hi = len;

    const float* Ab = g_a + (size_t)b * TT * NN;
    const float* Bb = g_b + (size_t)b * TT * NN;
    const int*   Yb = y_true + (size_t)b * TT;

    float part = 0.f;
    for (int t = t_lo + tid; t < t_hi; t += 256) {
        const float4* A4 = reinterpret_cast<const float4*>(Ab + (size_t)t * NN);
        const float4* B4 = reinterpret_cast<const float4*>(Bb + (size_t)t * NN);
        int y = Yb[t];
        float s = 0.f;
        float py = 0.f;
        #pragma unroll
        for (int q = 0; q < 8; q++) {
            float4 av = __ldcs(&A4[q]);
            float4 bv = __ldcs(&B4[q]);
            s += av.x * bv.x + av.y * bv.y + av.z * bv.z + av.w * bv.w;
            if (q == (y >> 2)) {
                float ae = (y & 3) == 0 ? av.x : (y & 3) == 1 ? av.y : (y & 3) == 2 ? av.z : av.w;
                float be = (y & 3) == 0 ? bv.x : (y & 3) == 1 ? bv.y : (y & 3) == 2 ? bv.z : bv.w;
                py = ae * be;
            }
        }
        part += __fdividef(py, s);
    }

    #pragma unroll
    for (int off = 16; off > 0; off >>= 1)
        part += __shfl_down_sync(FULL, part, off);

    __shared__ float red[8];
    if ((tid & 31) == 0) red[tid >> 5] = part;
    __syncthreads();
    if (tid == 0) {
        float s = 0.f;
        #pragma unroll
        for (int w = 0; w < 8; w++) s += red[w];
        g_partial[b][c] = s;
    }
}

// ---------------------------------------------------------------------------
__global__ void finalize_kernel(const int* __restrict__ lengths,
                                float* __restrict__ out)
{
    const int b = threadIdx.x;
    if (b >= BB) return;
    float inter = 0.f;
    #pragma unroll
    for (int c = 0; c < NCHUNK; c++) inter += g_partial[b][c];
    float flen = (float)lengths[b];
    float dice = (2.0f * inter + 1.0f) / (2.0f * flen + 1.0f);
    out[b] = 1.0f - dice;
}

// ---------------------------------------------------------------------------
extern "C" void kernel_launch(void* const* d_in, const int* in_sizes, int n_in,
                              void* d_out, int out_size)
{
    const float* pots    = (const float*)d_in[0];   // [B,T,N] fp32
    const int*   y_true  = (const int*)  d_in[1];   // [B,T] int32
    const int*   lengths = (const int*)  d_in[2];   // [B] int32
    const float* trans   = (const float*)d_in[3];   // [N,N] fp32
    float* out = (float*)d_out;                     // [B] fp32

    fb_kernel<<<2 * BB, 32>>>(pots, lengths, trans);
    combine_kernel<<<dim3(BB, NCHUNK), 256>>>(y_true, lengths);
    finalize_kernel<<<1, 128>>>(lengths, out);
}

// round 5
// speedup vs baseline: 11.1397x; 4.9192x over previous
#include <cuda_runtime.h>
#include <cstdint>

#define BB 128
#define TT 4096
#define NN 32
#define FULL 0xffffffffu
#define KSEG 32                 // segments per chain
#define SEGLEN (TT / KSEG)      // 128
#define WARM 48                 // warm-up steps (Hilbert contraction burn-in)
#define NCHUNK 8
#define CHUNK (TT / NCHUNK)

// Scratch tapes for scaled forward/backward messages (scale cancels in ratios).
__device__ float g_a[(size_t)BB * TT * NN];
__device__ float g_b[(size_t)BB * TT * NN];
__device__ float g_partial[BB][NCHUNK];

// ---------------------------------------------------------------------------
// Kernel 1: segmented forward/backward recursions, one warp per
// (batch, direction, segment). Lane = state.
// Probability-domain recursion with per-step rescale by lane 0 (any per-t
// positive scale cancels in the marginal ratio -> no log/lse anywhere).
// Mid-chain segments start WARM steps early from a uniform positive vector;
// diag(P)*E^T is a positive map, so the direction error contracts by
// ~tanh(range(trans)/4) < 0.5 per step => < 1e-14 after 48 steps. Segments
// whose warm-up window reaches the chain boundary use the exact boundary init.
// ---------------------------------------------------------------------------
__global__ void __launch_bounds__(32)
fb_kernel(const float* __restrict__ pots,
          const int*   __restrict__ lengths,
          const float* __restrict__ trans)
{
    const int lane = threadIdx.x;
    const int bid  = blockIdx.x;              // [0, 2*BB*KSEG)
    const int b    = bid >> 6;                 // / (2*KSEG)
    const int rem  = bid & 63;
    const int seg  = rem >> 1;
    const bool fwd = (rem & 1) == 0;

    const int len = lengths[b];
    const int t0  = seg * SEGLEN;
    if (t0 >= len) return;                     // segment beyond this chain
    int t1 = t0 + SEGLEN; if (t1 > len) t1 = len;

    const float* pot = pots + (size_t)b * TT * NN;

    float E[NN];

    if (fwd) {
        // lane j holds exp(trans[:, j]) ; a_new_j = sum_i a_i E_ij, * P_j
        #pragma unroll
        for (int i = 0; i < NN; i++) E[i] = __expf(trans[i * NN + lane]);

        float* A = g_a + (size_t)b * TT * NN;

        int tstart = t0 - WARM; if (tstart < 0) tstart = 0;
        float a = (tstart == 0) ? __expf(pot[lane]) : 1.0f;
        if (tstart >= t0) A[(size_t)tstart * NN + lane] = a;   // only t0==0

        // prefetch pot row for first step
        float pr = pot[(size_t)(tstart + 1) * NN + lane];

        for (int t = tstart + 1; t < t1; ++t) {
            float P = __expf(pr);
            int tn = t + 1; if (tn > TT - 1) tn = TT - 1;
            pr = pot[(size_t)tn * NN + lane];                  // prefetch next

            float acc0 = 0.f, acc1 = 0.f, acc2 = 0.f, acc3 = 0.f;
            float r = 0.f;
            #pragma unroll
            for (int i = 0; i < NN; i += 4) {
                float v0 = __shfl_sync(FULL, a, i + 0);
                float v1 = __shfl_sync(FULL, a, i + 1);
                float v2 = __shfl_sync(FULL, a, i + 2);
                float v3 = __shfl_sync(FULL, a, i + 3);
                if (i == 0) r = __frcp_rn(v0);                 // renorm
                acc0 = fmaf(v0, E[i + 0], acc0);
                acc1 = fmaf(v1, E[i + 1], acc1);
                acc2 = fmaf(v2, E[i + 2], acc2);
                acc3 = fmaf(v3, E[i + 3], acc3);
            }
            float s = (acc0 + acc1) + (acc2 + acc3);
            a = s * r * P;
            if (t >= t0) A[(size_t)t * NN + lane] = a;
        }
    } else {
        // lane i holds exp(trans[i, :]) ; b_i = sum_j E_ij (b_j * P_j)
        #pragma unroll
        for (int j = 0; j < NN; j++) E[j] = __expf(trans[lane * NN + j]);

        float* Bv = g_b + (size_t)b * TT * NN;

        int tstart = t1 - 1 + WARM; if (tstart > len - 1) tstart = len - 1;
        float bv = 1.0f;            // exact at len-1; warm-up init elsewhere
        if (tstart < t1) Bv[(size_t)tstart * NN + lane] = 1.0f; // only t1==len

        float pr = pot[(size_t)tstart * NN + lane];

        for (int t = tstart; t >= t0 + 1; --t) {
            float P = __expf(pr);
            int tn = t - 1; if (tn < 0) tn = 0;
            pr = pot[(size_t)tn * NN + lane];                  // prefetch next

            float u = bv * P;

            float acc0 = 0.f, acc1 = 0.f, acc2 = 0.f, acc3 = 0.f;
            float r = 0.f;
            #pragma unroll
            for (int j = 0; j < NN; j += 4) {
                float v0 = __shfl_sync(FULL, u, j + 0);
                float v1 = __shfl_sync(FULL, u, j + 1);
                float v2 = __shfl_sync(FULL, u, j + 2);
                float v3 = __shfl_sync(FULL, u, j + 3);
                if (j == 0) r = __frcp_rn(v0);
                acc0 = fmaf(v0, E[j + 0], acc0);
                acc1 = fmaf(v1, E[j + 1], acc1);
                acc2 = fmaf(v2, E[j + 2], acc2);
                acc3 = fmaf(v3, E[j + 3], acc3);
            }
            float s = (acc0 + acc1) + (acc2 + acc3);
            bv = s * r;
            if (t - 1 < t1) Bv[(size_t)(t - 1) * NN + lane] = bv;
        }
    }
}

// ---------------------------------------------------------------------------
// Kernel 2: combine partials. grid (BB, NCHUNK); block (b,c) handles
// t in [c*CHUNK, (c+1)*CHUNK) ∩ [0,len). Deterministic per-slot partials.
// p_t(y_t) = a_y b_y / sum_k a_k b_k (per-t scales cancel).
// ---------------------------------------------------------------------------
__global__ void __launch_bounds__(256)
combine_kernel(const int* __restrict__ y_true,
               const int* __restrict__ lengths)
{
    const int b   = blockIdx.x;
    const int c   = blockIdx.y;
    const int tid = threadIdx.x;
    const int len = lengths[b];

    const int t_lo = c * CHUNK;
    int t_hi = t_lo + CHUNK; if (t_hi > len) t_hi = len;

    const float* Ab = g_a + (size_t)b * TT * NN;
    const float* Bb = g_b + (size_t)b * TT * NN;
    const int*   Yb = y_true + (size_t)b * TT;

    float part = 0.f;
    for (int t = t_lo + tid; t < t_hi; t += 256) {
        const float4* A4 = reinterpret_cast<const float4*>(Ab + (size_t)t * NN);
        const float4* B4 = reinterpret_cast<const float4*>(Bb + (size_t)t * NN);
        int y = Yb[t];
        float s = 0.f;
        float py = 0.f;
        #pragma unroll
        for (int q = 0; q < 8; q++) {
            float4 av = __ldcs(&A4[q]);
            float4 bv = __ldcs(&B4[q]);
            s += av.x * bv.x + av.y * bv.y + av.z * bv.z + av.w * bv.w;
            if (q == (y >> 2)) {
                float ae = (y & 3) == 0 ? av.x : (y & 3) == 1 ? av.y : (y & 3) == 2 ? av.z : av.w;
                float be = (y & 3) == 0 ? bv.x : (y & 3) == 1 ? bv.y : (y & 3) == 2 ? bv.z : bv.w;
                py = ae * be;
            }
        }
        part += __fdividef(py, s);
    }

    #pragma unroll
    for (int off = 16; off > 0; off >>= 1)
        part += __shfl_down_sync(FULL, part, off);

    __shared__ float red[8];
    if ((tid & 31) == 0) red[tid >> 5] = part;
    __syncthreads();
    if (tid == 0) {
        float s = 0.f;
        #pragma unroll
        for (int w = 0; w < 8; w++) s += red[w];
        g_partial[b][c] = s;
    }
}

// ---------------------------------------------------------------------------
__global__ void finalize_kernel(const int* __restrict__ lengths,
                                float* __restrict__ out)
{
    const int b = threadIdx.x;
    if (b >= BB) return;
    float inter = 0.f;
    #pragma unroll
    for (int c = 0; c < NCHUNK; c++) inter += g_partial[b][c];
    float flen = (float)lengths[b];
    float dice = (2.0f * inter + 1.0f) / (2.0f * flen + 1.0f);
    out[b] = 1.0f - dice;
}

// ---------------------------------------------------------------------------
extern "C" void kernel_launch(void* const* d_in, const int* in_sizes, int n_in,
                              void* d_out, int out_size)
{
    const float* pots    = (const float*)d_in[0];   // [B,T,N] fp32
    const int*   y_true  = (const int*)  d_in[1];   // [B,T] int32
    const int*   lengths = (const int*)  d_in[2];   // [B] int32
    const float* trans   = (const float*)d_in[3];   // [N,N] fp32
    float* out = (float*)d_out;                     // [B] fp32

    fb_kernel<<<2 * BB * KSEG, 32>>>(pots, lengths, trans);
    combine_kernel<<<dim3(BB, NCHUNK), 256>>>(y_true, lengths);
    finalize_kernel<<<1, 128>>>(lengths, out);
}

// round 6
// speedup vs baseline: 14.0091x; 1.2576x over previous
#include <cuda_runtime.h>
#include <cstdint>

#define BB 128
#define TT 4096
#define NN 32
#define FULL 0xffffffffu
#define KSEG 32                 // segments per chain
#define SEGLEN (TT / KSEG)      // 128
#define WARM 20                 // warm-up steps (Hilbert contraction burn-in)
#define NCHUNK 8
#define CHUNK (TT / NCHUNK)

// Scratch tapes for scaled forward/backward messages (scale cancels in ratios).
__device__ float g_a[(size_t)BB * TT * NN];
__device__ float g_b[(size_t)BB * TT * NN];
__device__ float g_partial[BB][NCHUNK];

// One matvec step: share v across the warp via smem ping-pong, then
// y_lane = sum_i v_i * E2[lane-column pairs], using packed f32x2 FMAs.
// Returns s * rcp(v_0)  (renormalized dot), all lanes.
__device__ __forceinline__ float matvec_step(float v, float (*buf)[NN],
                                             int p, int lane,
                                             const unsigned long long* E2)
{
    buf[p][lane] = v;
    __syncwarp();
    const float* row = &buf[p][0];
    float r = __frcp_rn(row[0]);                      // renorm, off critical path
    unsigned long long acc0 = 0ull, acc1 = 0ull, acc2 = 0ull, acc3 = 0ull;
    const float2* row2 = reinterpret_cast<const float2*>(row);
    #pragma unroll
    for (int k = 0; k < 16; k += 4) {
        float2 w0 = row2[k + 0];
        float2 w1 = row2[k + 1];
        float2 w2 = row2[k + 2];
        float2 w3 = row2[k + 3];
        unsigned long long wv0, wv1, wv2, wv3;
        asm("mov.b64 %0, {%1, %2};" : "=l"(wv0) : "f"(w0.x), "f"(w0.y));
        asm("mov.b64 %0, {%1, %2};" : "=l"(wv1) : "f"(w1.x), "f"(w1.y));
        asm("mov.b64 %0, {%1, %2};" : "=l"(wv2) : "f"(w2.x), "f"(w2.y));
        asm("mov.b64 %0, {%1, %2};" : "=l"(wv3) : "f"(w3.x), "f"(w3.y));
        asm("fma.rn.f32x2 %0, %1, %2, %0;" : "+l"(acc0) : "l"(wv0), "l"(E2[k + 0]));
        asm("fma.rn.f32x2 %0, %1, %2, %0;" : "+l"(acc1) : "l"(wv1), "l"(E2[k + 1]));
        asm("fma.rn.f32x2 %0, %1, %2, %0;" : "+l"(acc2) : "l"(wv2), "l"(E2[k + 2]));
        asm("fma.rn.f32x2 %0, %1, %2, %0;" : "+l"(acc3) : "l"(wv3), "l"(E2[k + 3]));
    }
    asm("add.rn.f32x2 %0, %0, %1;" : "+l"(acc0) : "l"(acc1));
    asm("add.rn.f32x2 %0, %0, %1;" : "+l"(acc2) : "l"(acc3));
    asm("add.rn.f32x2 %0, %0, %1;" : "+l"(acc0) : "l"(acc2));
    float lo, hi;
    asm("mov.b64 {%0, %1}, %2;" : "=f"(lo), "=f"(hi) : "l"(acc0));
    return (lo + hi) * r;
}

// ---------------------------------------------------------------------------
// Kernel 1: segmented forward/backward recursions, one warp per
// (batch, direction, segment). Lane = state.
// Probability-domain recursion with per-step rescale by lane 0 (any per-t
// positive scale cancels in the marginal ratio -> no log/lse anywhere).
// Mid-chain segments start WARM steps early from a uniform positive vector;
// diag(P)*E^T is positive, so direction error contracts ~0.32x/step
// (Hilbert metric) => ~1e-10 after 20 steps. Segments whose warm-up window
// reaches a chain boundary use the exact boundary init.
// ---------------------------------------------------------------------------
__global__ void __launch_bounds__(32)
fb_kernel(const float* __restrict__ pots,
          const int*   __restrict__ lengths,
          const float* __restrict__ trans)
{
    __shared__ float buf[2][NN];

    const int lane = threadIdx.x;
    const int bid  = blockIdx.x;               // [0, 2*BB*KSEG)
    const int b    = bid >> 6;                 // / (2*KSEG)
    const int rem  = bid & 63;
    const int seg  = rem >> 1;
    const bool fwd = (rem & 1) == 0;

    const int len = lengths[b];
    const int t0  = seg * SEGLEN;
    if (t0 >= len) return;                     // segment beyond this chain
    int t1 = t0 + SEGLEN; if (t1 > len) t1 = len;

    const float* pot = pots + (size_t)b * TT * NN;
    unsigned long long E2[16];                 // packed exp(trans) pairs

    if (fwd) {
        // pair k packs exp(trans[2k][lane]), exp(trans[2k+1][lane])
        #pragma unroll
        for (int k = 0; k < 16; k++) {
            float e0 = __expf(trans[(2 * k)     * NN + lane]);
            float e1 = __expf(trans[(2 * k + 1) * NN + lane]);
            asm("mov.b64 %0, {%1, %2};" : "=l"(E2[k]) : "f"(e0), "f"(e1));
        }

        float* A = g_a + (size_t)b * TT * NN;

        int tstart = t0 - WARM; if (tstart < 0) tstart = 0;
        float a;
        if (tstart == 0) {
            a = __expf(pot[lane]);
            if (t0 == 0) A[lane] = a;
        } else {
            a = 1.0f;
        }

        float pr = pot[(size_t)(tstart + 1) * NN + lane];
        int t = tstart + 1;

        // warm-up (no stores)
        for (; t < t0; ++t) {
            float P = __expf(pr);
            pr = pot[(size_t)(t + 1) * NN + lane];
            float s = matvec_step(a, buf, t & 1, lane, E2);
            a = s * P;
        }
        // main (stores)
        for (; t < t1; ++t) {
            float P = __expf(pr);
            int tn = t + 1; if (tn > TT - 1) tn = TT - 1;
            pr = pot[(size_t)tn * NN + lane];
            float s = matvec_step(a, buf, t & 1, lane, E2);
            a = s * P;
            __stcs(&A[(size_t)t * NN + lane], a);
        }
    } else {
        // pair k packs exp(trans[lane][2k]), exp(trans[lane][2k+1])
        #pragma unroll
        for (int k = 0; k < 16; k++) {
            float e0 = __expf(trans[lane * NN + 2 * k]);
            float e1 = __expf(trans[lane * NN + 2 * k + 1]);
            asm("mov.b64 %0, {%1, %2};" : "=l"(E2[k]) : "f"(e0), "f"(e1));
        }

        float* Bv = g_b + (size_t)b * TT * NN;

        int tstart = t1 - 1 + WARM; if (tstart > len - 1) tstart = len - 1;
        float bv = 1.0f;                       // exact at len-1
        if (tstart < t1) Bv[(size_t)tstart * NN + lane] = 1.0f;

        float pr = pot[(size_t)tstart * NN + lane];
        int t = tstart;

        // warm-up: produce b_{t-1} for t-1 >= t1 (no stores)
        for (; t > t1; --t) {
            float P = __expf(pr);
            pr = pot[(size_t)(t - 1) * NN + lane];
            float s = matvec_step(bv * P, buf, t & 1, lane, E2);
            bv = s;
        }
        // main: produce and store b_{t-1} for t-1 in [t0, t1)
        for (; t >= t0 + 1; --t) {
            float P = __expf(pr);
            int tn = t - 1; if (tn < 0) tn = 0;
            pr = pot[(size_t)tn * NN + lane];
            float s = matvec_step(bv * P, buf, t & 1, lane, E2);
            bv = s;
            __stcs(&Bv[(size_t)(t - 1) * NN + lane], bv);
        }
    }
}

// ---------------------------------------------------------------------------
// Kernel 2: combine partials. grid (BB, NCHUNK); block (b,c) handles
// t in [c*CHUNK, (c+1)*CHUNK) ∩ [0,len). Deterministic per-slot partials.
// p_t(y_t) = a_y b_y / sum_k a_k b_k (per-t scales cancel).
// ---------------------------------------------------------------------------
__global__ void __launch_bounds__(256)
combine_kernel(const int* __restrict__ y_true,
               const int* __restrict__ lengths)
{
    const int b   = blockIdx.x;
    const int c   = blockIdx.y;
    const int tid = threadIdx.x;
    const int len = lengths[b];

    const int t_lo = c * CHUNK;
    int t_hi = t_lo + CHUNK; if (t_hi > len) t_hi = len;

    const float* Ab = g_a + (size_t)b * TT * NN;
    const float* Bb = g_b + (size_t)b * TT * NN;
    const int*   Yb = y_true + (size_t)b * TT;

    float part = 0.f;
    for (int t = t_lo + tid; t < t_hi; t += 256) {
        const float4* A4 = reinterpret_cast<const float4*>(Ab + (size_t)t * NN);
        const float4* B4 = reinterpret_cast<const float4*>(Bb + (size_t)t * NN);
        int y = Yb[t];
        float s = 0.f;
        float py = 0.f;
        #pragma unroll
        for (int q = 0; q < 8; q++) {
            float4 av = __ldcs(&A4[q]);
            float4 bv = __ldcs(&B4[q]);
            s += av.x * bv.x + av.y * bv.y + av.z * bv.z + av.w * bv.w;
            if (q == (y >> 2)) {
                float ae = (y & 3) == 0 ? av.x : (y & 3) == 1 ? av.y : (y & 3) == 2 ? av.z : av.w;
                float be = (y & 3) == 0 ? bv.x : (y & 3) == 1 ? bv.y : (y & 3) == 2 ? bv.z : bv.w;
                py = ae * be;
            }
        }
        part += __fdividef(py, s);
    }

    #pragma unroll
    for (int off = 16; off > 0; off >>= 1)
        part += __shfl_down_sync(FULL, part, off);

    __shared__ float red[8];
    if ((tid & 31) == 0) red[tid >> 5] = part;
    __syncthreads();
    if (tid == 0) {
        float s = 0.f;
        #pragma unroll
        for (int w = 0; w < 8; w++) s += red[w];
        g_partial[b][c] = s;
    }
}

// ---------------------------------------------------------------------------
__global__ void finalize_kernel(const int* __restrict__ lengths,
                                float* __restrict__ out)
{
    const int b = threadIdx.x;
    if (b >= BB) return;
    float inter = 0.f;
    #pragma unroll
    for (int c = 0; c < NCHUNK; c++) inter += g_partial[b][c];
    float flen = (float)lengths[b];
    float dice = (2.0f * inter + 1.0f) / (2.0f * flen + 1.0f);
    out[b] = 1.0f - dice;
}

// ---------------------------------------------------------------------------
extern "C" void kernel_launch(void* const* d_in, const int* in_sizes, int n_in,
                              void* d_out, int out_size)
{
    const float* pots    = (const float*)d_in[0];   // [B,T,N] fp32
    const int*   y_true  = (const int*)  d_in[1];   // [B,T] int32
    const int*   lengths = (const int*)  d_in[2];   // [B] int32
    const float* trans   = (const float*)d_in[3];   // [N,N] fp32
    float* out = (float*)d_out;                     // [B] fp32

    fb_kernel<<<2 * BB * KSEG, 32>>>(pots, lengths, trans);
    combine_kernel<<<dim3(BB, NCHUNK), 256>>>(y_true, lengths);
    finalize_kernel<<<1, 128>>>(lengths, out);
}